// round 1
// baseline (speedup 1.0000x reference)
#include <cuda_runtime.h>
#include <math.h>

#define B_  8
#define T_  2048
#define C_  3
#define E_  256
#define K_  15
#define D_  5
#define BN_ 32

// ---------------- scratch (device globals; no allocs allowed) ----------------
static __device__ float g_mean[B_*C_];
static __device__ float g_std [B_*C_];
static __device__ float g_qn[B_*C_*T_];
static __device__ float g_kn[B_*C_*T_];
static __device__ float g_h0[B_*BN_*T_];
static __device__ float g_h1[B_*BN_*T_];
static __device__ float g_q[(size_t)B_*T_*E_];
static __device__ float g_k[(size_t)B_*T_*E_];
static __device__ float g_v[(size_t)B_*T_*E_];
static __device__ float g_attn[(size_t)B_*T_*T_];   // 128 MiB
static __device__ float g_o[(size_t)B_*T_*E_];

// ---------------- RevIN stats over time of key_in ----------------
__global__ void k_stats(const float* __restrict__ key){
    int bc = blockIdx.x, b = bc / C_, c = bc % C_;
    int tid = threadIdx.x;
    float s = 0.f, ss = 0.f;
    for (int t = tid; t < T_; t += 256){
        float x = key[((size_t)b*T_ + t)*C_ + c];
        s += x; ss += x*x;
    }
    __shared__ float r1[256], r2[256];
    r1[tid]=s; r2[tid]=ss; __syncthreads();
    for(int o=128;o;o>>=1){ if(tid<o){ r1[tid]+=r1[tid+o]; r2[tid]+=r2[tid+o]; } __syncthreads(); }
    if(tid==0){
        float m = r1[0]/(float)T_;
        float v = r2[0]/(float)T_ - m*m;
        g_mean[bc]=m;
        g_std[bc]=sqrtf(v + 1e-5f);
    }
}

// ---------------- normalize + transpose to [B][C][T] ----------------
__global__ void k_norm(const float* __restrict__ q, const float* __restrict__ k,
                       const float* __restrict__ rw, const float* __restrict__ rb){
    int i = blockIdx.x*256 + threadIdx.x;
    if(i >= B_*C_*T_) return;
    int t = i % T_, c = (i / T_) % C_, b = i / (C_*T_);
    float m = g_mean[b*C_+c], inv = 1.f/g_std[b*C_+c];
    float w = rw[c], bb = rb[c];
    size_t src = ((size_t)b*T_ + t)*C_ + c;
    g_qn[i] = (q[src]-m)*inv*w + bb;
    g_kn[i] = (k[src]-m)*inv*w + bb;
}

// ---------------- conv in: C_ -> BN_, K=15, dil=1, relu ----------------
__global__ void k_conv_in(const float* __restrict__ src, const float* __restrict__ w,
                          const float* __restrict__ bias, float* __restrict__ dst){
    __shared__ float ws[BN_*C_*K_];     // 1440
    __shared__ float bs[BN_];
    __shared__ float xs[C_][256 + K_ - 1];
    int b = blockIdx.x, t0 = blockIdx.y*256, tid = threadIdx.x;
    for(int i=tid;i<BN_*C_*K_;i+=256) ws[i]=w[i];
    if(tid<BN_) bs[tid]=bias[tid];
    const int W = 256 + K_ - 1;
    for(int i=tid;i<C_*W;i+=256){
        int ci=i/W, p=i%W, g=t0+p-7;
        xs[ci][p] = ((unsigned)g < T_) ? src[(b*C_+ci)*T_ + g] : 0.f;
    }
    __syncthreads();
    float acc[BN_];
    #pragma unroll
    for(int c=0;c<BN_;c++) acc[c]=bs[c];
    #pragma unroll
    for(int ci=0;ci<C_;ci++){
        #pragma unroll
        for(int k=0;k<K_;k++){
            float x = xs[ci][tid+k];
            #pragma unroll
            for(int c=0;c<BN_;c++) acc[c] += x * ws[(c*C_+ci)*K_+k];
        }
    }
    int t = t0 + tid;
    #pragma unroll
    for(int c=0;c<BN_;c++) dst[((size_t)b*BN_+c)*T_ + t] = fmaxf(acc[c], 0.f);
}

// ---------------- conv mid: BN_ -> BN_, K=15, dilated, relu ----------------
__global__ void k_conv_mid(const float* __restrict__ src, const float* __restrict__ w,
                           const float* __restrict__ bias, float* __restrict__ dst, int dil){
    extern __shared__ float sm[];
    float* ws = sm;                      // 15360 floats
    float* xs = sm + BN_*BN_*K_;         // 32 * (128 + 14*dil)
    int b = blockIdx.x, t0 = blockIdx.y*128, tid = threadIdx.x;
    int H = 7*dil, W = 128 + 14*dil;
    for(int i=tid;i<BN_*BN_*K_;i+=128) ws[i]=w[i];
    for(int i=tid;i<BN_*W;i+=128){
        int ci = i/W, p = i - ci*W, g = t0 - H + p;
        xs[i] = ((unsigned)g < T_) ? src[(b*BN_+ci)*T_ + g] : 0.f;
    }
    __syncthreads();
    float acc[BN_];
    #pragma unroll
    for(int c=0;c<BN_;c++) acc[c]=__ldg(&bias[c]);
    for(int ci=0;ci<BN_;ci++){
        const float* xr = xs + ci*W + tid;
        const float* wr = ws + ci*K_;
        #pragma unroll
        for(int k=0;k<K_;k++){
            float x = xr[k*dil];
            #pragma unroll
            for(int c=0;c<BN_;c++) acc[c] += x * wr[c*(BN_*K_) + k];
        }
    }
    int t = t0 + tid;
    #pragma unroll
    for(int c=0;c<BN_;c++) dst[((size_t)b*BN_+c)*T_ + t] = fmaxf(acc[c], 0.f);
}

// ---------------- conv out (1x1): BN_ -> E_, write [B][T][E] ----------------
__global__ void k_conv_out(const float* __restrict__ src, const float* __restrict__ w,
                           const float* __restrict__ bias, float* __restrict__ dst){
    __shared__ float xs[BN_][32];
    int b = blockIdx.x, t0 = blockIdx.y*32, e = threadIdx.x;
    for(int i=e;i<BN_*32;i+=256){
        int ci=i>>5, tl=i&31;
        xs[ci][tl] = src[((size_t)b*BN_+ci)*T_ + t0 + tl];
    }
    __syncthreads();
    float acc[32];
    float bb = bias[e];
    #pragma unroll
    for(int t=0;t<32;t++) acc[t]=bb;
    #pragma unroll 4
    for(int ci=0;ci<BN_;ci++){
        float wv = __ldg(&w[e*BN_+ci]);
        #pragma unroll
        for(int t=0;t<32;t++) acc[t] += xs[ci][t]*wv;
    }
    #pragma unroll
    for(int t=0;t<32;t++) dst[((size_t)b*T_ + t0+t)*E_ + e] = acc[t];
}

// ---------------- tiled fp32 GEMMs (64x64x16, 4x4 micro) ----------------
#define GBM 64
#define GBN 64
#define GBK 16

// C[M,N] = alpha * A[M,K] * B[N,K]^T   (both row-major, K contiguous)
__global__ void k_gemm_nt(const float* __restrict__ A, const float* __restrict__ Bm,
                          float* __restrict__ Cm, int M, int N, int K,
                          size_t sA, size_t sB, size_t sC, float alpha){
    __shared__ float As[GBK][GBM+4];
    __shared__ float Bs[GBK][GBN+4];
    int bz = blockIdx.z;
    A += bz*sA; Bm += bz*sB; Cm += bz*sC;
    int tid = threadIdx.x;
    int ty = tid>>4, tx = tid&15;
    int row0 = blockIdx.x*GBM, col0 = blockIdx.y*GBN;
    float acc[4][4] = {};
    int lr = tid>>2, lc = (tid&3)*4;
    for(int k0=0;k0<K;k0+=GBK){
        float4 av = *(const float4*)(A  + (size_t)(row0+lr)*K + k0 + lc);
        float4 bv = *(const float4*)(Bm + (size_t)(col0+lr)*K + k0 + lc);
        As[lc+0][lr]=av.x; As[lc+1][lr]=av.y; As[lc+2][lr]=av.z; As[lc+3][lr]=av.w;
        Bs[lc+0][lr]=bv.x; Bs[lc+1][lr]=bv.y; Bs[lc+2][lr]=bv.z; Bs[lc+3][lr]=bv.w;
        __syncthreads();
        #pragma unroll
        for(int kk=0;kk<GBK;kk++){
            float a[4], bb[4];
            #pragma unroll
            for(int i=0;i<4;i++) a[i]=As[kk][ty*4+i];
            #pragma unroll
            for(int j=0;j<4;j++) bb[j]=Bs[kk][tx*4+j];
            #pragma unroll
            for(int i=0;i<4;i++)
                #pragma unroll
                for(int j=0;j<4;j++) acc[i][j] += a[i]*bb[j];
        }
        __syncthreads();
    }
    #pragma unroll
    for(int i=0;i<4;i++){
        float4 v = make_float4(acc[i][0]*alpha, acc[i][1]*alpha, acc[i][2]*alpha, acc[i][3]*alpha);
        *(float4*)(Cm + (size_t)(row0+ty*4+i)*N + col0 + tx*4) = v;
    }
}

// C[M,N] = A[M,K] * B[K,N]   (row-major)
__global__ void k_gemm_nn(const float* __restrict__ A, const float* __restrict__ Bm,
                          float* __restrict__ Cm, int M, int N, int K,
                          size_t sA, size_t sB, size_t sC){
    __shared__ float As[GBK][GBM+4];
    __shared__ float Bs[GBK][GBN+4];
    int bz = blockIdx.z;
    A += bz*sA; Bm += bz*sB; Cm += bz*sC;
    int tid = threadIdx.x;
    int ty = tid>>4, tx = tid&15;
    int row0 = blockIdx.x*GBM, col0 = blockIdx.y*GBN;
    float acc[4][4] = {};
    int lr = tid>>2, lc = (tid&3)*4;     // A tile load
    int kr = tid>>4, nc = (tid&15)*4;    // B tile load
    for(int k0=0;k0<K;k0+=GBK){
        float4 av = *(const float4*)(A  + (size_t)(row0+lr)*K + k0 + lc);
        float4 bv = *(const float4*)(Bm + (size_t)(k0+kr)*N + col0 + nc);
        As[lc+0][lr]=av.x; As[lc+1][lr]=av.y; As[lc+2][lr]=av.z; As[lc+3][lr]=av.w;
        *(float4*)&Bs[kr][nc] = bv;
        __syncthreads();
        #pragma unroll
        for(int kk=0;kk<GBK;kk++){
            float a[4], bb[4];
            #pragma unroll
            for(int i=0;i<4;i++) a[i]=As[kk][ty*4+i];
            #pragma unroll
            for(int j=0;j<4;j++) bb[j]=Bs[kk][tx*4+j];
            #pragma unroll
            for(int i=0;i<4;i++)
                #pragma unroll
                for(int j=0;j<4;j++) acc[i][j] += a[i]*bb[j];
        }
        __syncthreads();
    }
    #pragma unroll
    for(int i=0;i<4;i++){
        float4 v = make_float4(acc[i][0], acc[i][1], acc[i][2], acc[i][3]);
        *(float4*)(Cm + (size_t)(row0+ty*4+i)*N + col0 + tx*4) = v;
    }
}

// ---------------- row softmax over T_ ----------------
__global__ void k_softmax(float* __restrict__ S){
    size_t row = blockIdx.x;
    float* p = S + row*T_;
    int tid = threadIdx.x;
    float v[8];
    #pragma unroll
    for(int j=0;j<8;j++) v[j] = p[tid + j*256];
    float m = v[0];
    #pragma unroll
    for(int j=1;j<8;j++) m = fmaxf(m, v[j]);
    __shared__ float sm[40];
    for(int o=16;o;o>>=1) m = fmaxf(m, __shfl_xor_sync(0xffffffffu, m, o));
    if((tid&31)==0) sm[tid>>5] = m;
    __syncthreads();
    if(tid<32){
        float t = (tid<8)?sm[tid]:-3.0e38f;
        for(int o=4;o;o>>=1) t=fmaxf(t,__shfl_xor_sync(0xffffffffu,t,o));
        if(tid==0) sm[32]=t;
    }
    __syncthreads();
    m = sm[32];
    float s=0.f;
    #pragma unroll
    for(int j=0;j<8;j++){ v[j]=__expf(v[j]-m); s+=v[j]; }
    for(int o=16;o;o>>=1) s += __shfl_xor_sync(0xffffffffu, s, o);
    if((tid&31)==0) sm[tid>>5] = s;
    __syncthreads();
    if(tid<32){
        float t=(tid<8)?sm[tid]:0.f;
        for(int o=4;o;o>>=1) t+=__shfl_xor_sync(0xffffffffu,t,o);
        if(tid==0) sm[33]=t;
    }
    __syncthreads();
    float inv = 1.f/sm[33];
    #pragma unroll
    for(int j=0;j<8;j++) p[tid+j*256]=v[j]*inv;
}

// ---------------- output proj + RevIN denorm ----------------
__global__ void k_final(const float* __restrict__ o, const float* __restrict__ w,
                        const float* __restrict__ ob, const float* __restrict__ rw,
                        const float* __restrict__ rb, float* __restrict__ out){
    int bt = blockIdx.x;
    int b  = bt >> 11;
    int e  = threadIdx.x;
    float x = o[(size_t)bt*E_ + e];
    float p0 = x*w[e], p1 = x*w[E_+e], p2 = x*w[2*E_+e];
    for(int s=16;s;s>>=1){
        p0 += __shfl_down_sync(0xffffffffu, p0, s);
        p1 += __shfl_down_sync(0xffffffffu, p1, s);
        p2 += __shfl_down_sync(0xffffffffu, p2, s);
    }
    __shared__ float sm[3][8];
    int wid=e>>5, lane=e&31;
    if(lane==0){ sm[0][wid]=p0; sm[1][wid]=p1; sm[2][wid]=p2; }
    __syncthreads();
    if(e < C_){
        float s=0.f;
        #pragma unroll
        for(int wdx=0;wdx<8;wdx++) s += sm[e][wdx];
        int c = e;
        float val = s + ob[c];
        val = (val - rb[c]) / rw[c];
        val = val * g_std[b*C_+c] + g_mean[b*C_+c];
        out[(size_t)bt*C_ + c] = val;
    }
}

// ---------------- host orchestration (graph-capturable) ----------------
extern "C" void kernel_launch(void* const* d_in, const int* in_sizes, int n_in,
                              void* d_out, int out_size){
    const float* query = (const float*)d_in[0];
    const float* key   = (const float*)d_in[1];
    const float* out_w = (const float*)d_in[20];
    const float* out_b = (const float*)d_in[21];
    const float* rw    = (const float*)d_in[22];
    const float* rb    = (const float*)d_in[23];

    float *p_qn,*p_kn,*p_h0,*p_h1,*p_q,*p_k,*p_v,*p_attn,*p_o;
    cudaGetSymbolAddress((void**)&p_qn,   g_qn);
    cudaGetSymbolAddress((void**)&p_kn,   g_kn);
    cudaGetSymbolAddress((void**)&p_h0,   g_h0);
    cudaGetSymbolAddress((void**)&p_h1,   g_h1);
    cudaGetSymbolAddress((void**)&p_q,    g_q);
    cudaGetSymbolAddress((void**)&p_k,    g_k);
    cudaGetSymbolAddress((void**)&p_v,    g_v);
    cudaGetSymbolAddress((void**)&p_attn, g_attn);
    cudaGetSymbolAddress((void**)&p_o,    g_o);

    cudaFuncSetAttribute(k_conv_mid, cudaFuncAttributeMaxDynamicSharedMemorySize, 160*1024);

    k_stats<<<B_*C_, 256>>>(key);
    k_norm<<<(B_*C_*T_ + 255)/256, 256>>>(query, key, rw, rb);

    float* qkv[3] = {p_q, p_k, p_v};
    for(int net=0; net<3; net++){
        const float* w_in  = (const float*)d_in[2+net*6+0];
        const float* b_in  = (const float*)d_in[2+net*6+1];
        const float* w_mid = (const float*)d_in[2+net*6+2];
        const float* b_mid = (const float*)d_in[2+net*6+3];
        const float* w_out = (const float*)d_in[2+net*6+4];
        const float* b_out = (const float*)d_in[2+net*6+5];
        const float* srcn  = (net==0) ? p_qn : p_kn;

        k_conv_in<<<dim3(B_, T_/256), 256>>>(srcn, w_in, b_in, p_h0);
        float* cur = p_h0; float* nxt = p_h1;
        for(int i=0;i<D_;i++){
            int dil = 2<<i;  // 2,4,8,16,32
            size_t smem = (size_t)(BN_*BN_*K_ + BN_*(128 + 14*dil)) * sizeof(float);
            k_conv_mid<<<dim3(B_, T_/128), 128, smem>>>(
                cur, w_mid + (size_t)i*BN_*BN_*K_, b_mid + i*BN_, nxt, dil);
            float* tmp=cur; cur=nxt; nxt=tmp;
        }
        k_conv_out<<<dim3(B_, T_/32), 256>>>(cur, w_out, b_out, qkv[net]);
    }

    // S = scale * Q K^T
    k_gemm_nt<<<dim3(T_/GBM, T_/GBN, B_), 256>>>(p_q, p_k, p_attn, T_, T_, E_,
        (size_t)T_*E_, (size_t)T_*E_, (size_t)T_*T_, 0.0625f);
    k_softmax<<<B_*T_, 256>>>(p_attn);
    // O = P V
    k_gemm_nn<<<dim3(T_/GBM, E_/GBN, B_), 256>>>(p_attn, p_v, p_o, T_, E_, T_,
        (size_t)T_*T_, (size_t)T_*E_, (size_t)T_*E_);
    k_final<<<B_*T_, 256>>>(p_o, out_w, out_b, rw, rb, (float*)d_out);
}

// round 2
// speedup vs baseline: 1.2797x; 1.2797x over previous
#include <cuda_runtime.h>
#include <math.h>

#define B_  8
#define T_  2048
#define C_  3
#define E_  256
#define K_  15
#define D_  5
#define BN_ 32
#define WSZ (BN_*BN_*K_)   // 15360 floats per mid layer

struct P3 { const float *q, *k, *v; };

__device__ __forceinline__ const float* pick(const P3& p, int net){
    return net==0 ? p.q : (net==1 ? p.k : p.v);
}

// ---------------- scratch (device globals; no allocs allowed) ----------------
static __device__ float g_mean[B_*C_];
static __device__ float g_std [B_*C_];
static __device__ float g_qn[B_*C_*T_];
static __device__ float g_kn[B_*C_*T_];
static __device__ float g_h0[3*B_*BN_*T_];
static __device__ float g_h1[3*B_*BN_*T_];
static __device__ float g_q[(size_t)B_*T_*E_];
static __device__ float g_k[(size_t)B_*T_*E_];
static __device__ float g_v[(size_t)B_*T_*E_];
static __device__ float g_attn[(size_t)B_*T_*T_];   // 128 MiB
static __device__ float g_o[(size_t)B_*T_*E_];

// ---------------- RevIN stats over time of key_in ----------------
__global__ void k_stats(const float* __restrict__ key){
    int bc = blockIdx.x, b = bc / C_, c = bc % C_;
    int tid = threadIdx.x;
    float s = 0.f, ss = 0.f;
    for (int t = tid; t < T_; t += 256){
        float x = key[((size_t)b*T_ + t)*C_ + c];
        s += x; ss += x*x;
    }
    __shared__ float r1[256], r2[256];
    r1[tid]=s; r2[tid]=ss; __syncthreads();
    for(int o=128;o;o>>=1){ if(tid<o){ r1[tid]+=r1[tid+o]; r2[tid]+=r2[tid+o]; } __syncthreads(); }
    if(tid==0){
        float m = r1[0]/(float)T_;
        float v = r2[0]/(float)T_ - m*m;
        g_mean[bc]=m;
        g_std[bc]=sqrtf(v + 1e-5f);
    }
}

// ---------------- normalize + transpose to [B][C][T] ----------------
__global__ void k_norm(const float* __restrict__ q, const float* __restrict__ k,
                       const float* __restrict__ rw, const float* __restrict__ rb){
    int i = blockIdx.x*256 + threadIdx.x;
    if(i >= B_*C_*T_) return;
    int t = i % T_, c = (i / T_) % C_, b = i / (C_*T_);
    float m = g_mean[b*C_+c], inv = 1.f/g_std[b*C_+c];
    float w = rw[c], bb = rb[c];
    size_t src = ((size_t)b*T_ + t)*C_ + c;
    g_qn[i] = (q[src]-m)*inv*w + bb;
    g_kn[i] = (k[src]-m)*inv*w + bb;
}

// ---------------- conv in (fused q/k/v): C_ -> BN_, K=15, dil=1, relu ------
__global__ void k_conv_in(const float* __restrict__ qn, const float* __restrict__ kn,
                          P3 w, P3 bias, float* __restrict__ dstbase){
    int net = blockIdx.z;
    const float* src = (net==0) ? qn : kn;
    const float* wp  = pick(w, net);
    const float* bp  = pick(bias, net);
    float* dst = dstbase + (size_t)net*B_*BN_*T_;

    __shared__ float ws[BN_*C_*K_];     // 1440
    __shared__ float bs[BN_];
    __shared__ float xs[C_][256 + K_ - 1];
    int b = blockIdx.y, t0 = blockIdx.x*256, tid = threadIdx.x;
    for(int i=tid;i<BN_*C_*K_;i+=256) ws[i]=wp[i];
    if(tid<BN_) bs[tid]=bp[tid];
    const int W = 256 + K_ - 1;
    for(int i=tid;i<C_*W;i+=256){
        int ci=i/W, p=i%W, g=t0+p-7;
        xs[ci][p] = ((unsigned)g < T_) ? src[(b*C_+ci)*T_ + g] : 0.f;
    }
    __syncthreads();
    float acc[BN_];
    #pragma unroll
    for(int c=0;c<BN_;c++) acc[c]=bs[c];
    #pragma unroll
    for(int ci=0;ci<C_;ci++){
        #pragma unroll
        for(int k=0;k<K_;k++){
            float x = xs[ci][tid+k];
            #pragma unroll
            for(int c=0;c<BN_;c++) acc[c] += x * ws[(c*C_+ci)*K_+k];
        }
    }
    int t = t0 + tid;
    #pragma unroll
    for(int c=0;c<BN_;c++) dst[((size_t)b*BN_+c)*T_ + t] = fmaxf(acc[c], 0.f);
}

// ---------------- conv mid (fused q/k/v): BN_ -> BN_, K=15, dilated, relu --
// weights transposed in smem to [ci][k][cout] so per-(ci,k) the 32 cout
// weights are contiguous -> 8x LDS.128 instead of 32x scalar LDS.
template<int DIL>
__global__ void k_conv_mid(const float* __restrict__ srcbase, P3 wm, P3 bm,
                           float* __restrict__ dstbase, int layer){
    constexpr int W = 128 + 14*DIL;
    constexpr int H = 7*DIL;
    extern __shared__ float sm[];
    float* ws = sm;           // WSZ floats, layout [ci*15+k][32]
    float* xs = sm + WSZ;     // 32 * W

    int net = blockIdx.z;
    const float* w    = pick(wm, net) + (size_t)layer*WSZ;
    const float* bias = pick(bm, net) + layer*BN_;
    const float* src  = srcbase + (size_t)net*B_*BN_*T_;
    float* dst        = dstbase + (size_t)net*B_*BN_*T_;

    int b = blockIdx.y, t0 = blockIdx.x*128, tid = threadIdx.x;

    for(int i=tid;i<WSZ;i+=128){
        int cout = i/480, rest = i - cout*480;
        ws[rest*BN_ + cout] = w[i];
    }
    for(int i=tid;i<BN_*W;i+=128){
        int ci = i/W, p = i - ci*W, g = t0 - H + p;
        xs[i] = ((unsigned)g < T_) ? src[(b*BN_+ci)*T_ + g] : 0.f;
    }
    __syncthreads();

    float acc[BN_];
    #pragma unroll
    for(int c=0;c<BN_;c++) acc[c]=__ldg(&bias[c]);

    for(int ci=0;ci<BN_;ci++){
        const float* xr = xs + ci*W + tid;
        #pragma unroll
        for(int k=0;k<K_;k++){
            float x = xr[k*DIL];
            const float4* wr = (const float4*)(ws + (ci*K_+k)*BN_);
            #pragma unroll
            for(int m=0;m<8;m++){
                float4 wv = wr[m];
                acc[4*m+0] += x*wv.x;
                acc[4*m+1] += x*wv.y;
                acc[4*m+2] += x*wv.z;
                acc[4*m+3] += x*wv.w;
            }
        }
    }
    int t = t0 + tid;
    #pragma unroll
    for(int c=0;c<BN_;c++) dst[((size_t)b*BN_+c)*T_ + t] = fmaxf(acc[c], 0.f);
}

// ---------------- conv out (fused, 1x1): BN_ -> E_, write [B][T][E] --------
__global__ void k_conv_out(const float* __restrict__ srcbase, P3 w, P3 bias,
                           float* __restrict__ qd, float* __restrict__ kd,
                           float* __restrict__ vd){
    int net = blockIdx.z;
    const float* src = srcbase + (size_t)net*B_*BN_*T_;
    const float* wp  = pick(w, net);
    const float* bp  = pick(bias, net);
    float* dst = (net==0) ? qd : (net==1 ? kd : vd);

    __shared__ float xs[BN_][32];
    int b = blockIdx.y, t0 = blockIdx.x*32, e = threadIdx.x;
    for(int i=e;i<BN_*32;i+=256){
        int ci=i>>5, tl=i&31;
        xs[ci][tl] = src[((size_t)b*BN_+ci)*T_ + t0 + tl];
    }
    __syncthreads();
    float acc[32];
    float bb = bp[e];
    #pragma unroll
    for(int t=0;t<32;t++) acc[t]=bb;
    #pragma unroll 4
    for(int ci=0;ci<BN_;ci++){
        float wv = __ldg(&wp[e*BN_+ci]);
        #pragma unroll
        for(int t=0;t<32;t++) acc[t] += xs[ci][t]*wv;
    }
    #pragma unroll
    for(int t=0;t<32;t++) dst[((size_t)b*T_ + t0+t)*E_ + e] = acc[t];
}

// ---------------- fp32 GEMM NT: 128x128 tile, 8x8 micro, BK=16 ----------------
// C[M,N] = alpha * A[M,K] * B[N,K]^T  (row-major, K contiguous)
__global__ void __launch_bounds__(256, 2)
k_gemm_nt(const float* __restrict__ A, const float* __restrict__ Bm,
          float* __restrict__ Cm, int M, int N, int K,
          size_t sA, size_t sB, size_t sC, float alpha){
    __shared__ float As[16][132];
    __shared__ float Bs[16][132];
    int bz = blockIdx.z;
    A += bz*sA; Bm += bz*sB; Cm += bz*sC;
    int tid = threadIdx.x;
    int ty = tid>>4, tx = tid&15;
    int row0 = blockIdx.x*128, col0 = blockIdx.y*128;
    float acc[8][8] = {};
    for(int k0=0;k0<K;k0+=16){
        #pragma unroll
        for(int j=0;j<2;j++){
            int idx = tid + j*256;
            int r = idx>>2, cc = (idx&3)*4;
            float4 av = *(const float4*)(A  + (size_t)(row0+r)*K + k0 + cc);
            float4 bv = *(const float4*)(Bm + (size_t)(col0+r)*K + k0 + cc);
            As[cc+0][r]=av.x; As[cc+1][r]=av.y; As[cc+2][r]=av.z; As[cc+3][r]=av.w;
            Bs[cc+0][r]=bv.x; Bs[cc+1][r]=bv.y; Bs[cc+2][r]=bv.z; Bs[cc+3][r]=bv.w;
        }
        __syncthreads();
        #pragma unroll
        for(int kk=0;kk<16;kk++){
            float a[8], bb[8];
            *(float4*)&a[0]  = *(const float4*)&As[kk][ty*8];
            *(float4*)&a[4]  = *(const float4*)&As[kk][ty*8+4];
            *(float4*)&bb[0] = *(const float4*)&Bs[kk][tx*8];
            *(float4*)&bb[4] = *(const float4*)&Bs[kk][tx*8+4];
            #pragma unroll
            for(int i=0;i<8;i++)
                #pragma unroll
                for(int j=0;j<8;j++) acc[i][j] += a[i]*bb[j];
        }
        __syncthreads();
    }
    #pragma unroll
    for(int i=0;i<8;i++){
        float* crow = Cm + (size_t)(row0+ty*8+i)*N + col0 + tx*8;
        float4 v0 = make_float4(acc[i][0]*alpha, acc[i][1]*alpha, acc[i][2]*alpha, acc[i][3]*alpha);
        float4 v1 = make_float4(acc[i][4]*alpha, acc[i][5]*alpha, acc[i][6]*alpha, acc[i][7]*alpha);
        *(float4*)crow = v0;
        *(float4*)(crow+4) = v1;
    }
}

// ---------------- fp32 GEMM NN: 128x64 tile, 8x4 micro, BK=16 ----------------
// C[M,N] = A[M,K] * B[K,N]  (row-major)
__global__ void __launch_bounds__(256, 2)
k_gemm_nn(const float* __restrict__ A, const float* __restrict__ Bm,
          float* __restrict__ Cm, int M, int N, int K,
          size_t sA, size_t sB, size_t sC){
    __shared__ float As[16][132];
    __shared__ float Bs[16][68];
    int bz = blockIdx.z;
    A += bz*sA; Bm += bz*sB; Cm += bz*sC;
    int tid = threadIdx.x;
    int ty = tid>>4, tx = tid&15;
    int row0 = blockIdx.x*128, col0 = blockIdx.y*64;
    float acc[8][4] = {};
    int br = tid>>4, bc = (tid&15)*4;   // B tile load: 16 x 64
    for(int k0=0;k0<K;k0+=16){
        #pragma unroll
        for(int j=0;j<2;j++){
            int idx = tid + j*256;
            int r = idx>>2, cc = (idx&3)*4;
            float4 av = *(const float4*)(A + (size_t)(row0+r)*K + k0 + cc);
            As[cc+0][r]=av.x; As[cc+1][r]=av.y; As[cc+2][r]=av.z; As[cc+3][r]=av.w;
        }
        *(float4*)&Bs[br][bc] = *(const float4*)(Bm + (size_t)(k0+br)*N + col0 + bc);
        __syncthreads();
        #pragma unroll
        for(int kk=0;kk<16;kk++){
            float a[8], bb[4];
            *(float4*)&a[0]  = *(const float4*)&As[kk][ty*8];
            *(float4*)&a[4]  = *(const float4*)&As[kk][ty*8+4];
            *(float4*)&bb[0] = *(const float4*)&Bs[kk][tx*4];
            #pragma unroll
            for(int i=0;i<8;i++)
                #pragma unroll
                for(int j=0;j<4;j++) acc[i][j] += a[i]*bb[j];
        }
        __syncthreads();
    }
    #pragma unroll
    for(int i=0;i<8;i++){
        float4 v = make_float4(acc[i][0], acc[i][1], acc[i][2], acc[i][3]);
        *(float4*)(Cm + (size_t)(row0+ty*8+i)*N + col0 + tx*4) = v;
    }
}

// ---------------- row softmax over T_ ----------------
__global__ void k_softmax(float* __restrict__ S){
    size_t row = blockIdx.x;
    float* p = S + row*T_;
    int tid = threadIdx.x;
    float v[8];
    #pragma unroll
    for(int j=0;j<8;j++) v[j] = p[tid + j*256];
    float m = v[0];
    #pragma unroll
    for(int j=1;j<8;j++) m = fmaxf(m, v[j]);
    __shared__ float sm[40];
    for(int o=16;o;o>>=1) m = fmaxf(m, __shfl_xor_sync(0xffffffffu, m, o));
    if((tid&31)==0) sm[tid>>5] = m;
    __syncthreads();
    if(tid<32){
        float t = (tid<8)?sm[tid]:-3.0e38f;
        for(int o=4;o;o>>=1) t=fmaxf(t,__shfl_xor_sync(0xffffffffu,t,o));
        if(tid==0) sm[32]=t;
    }
    __syncthreads();
    m = sm[32];
    float s=0.f;
    #pragma unroll
    for(int j=0;j<8;j++){ v[j]=__expf(v[j]-m); s+=v[j]; }
    for(int o=16;o;o>>=1) s += __shfl_xor_sync(0xffffffffu, s, o);
    if((tid&31)==0) sm[tid>>5] = s;
    __syncthreads();
    if(tid<32){
        float t=(tid<8)?sm[tid]:0.f;
        for(int o=4;o;o>>=1) t+=__shfl_xor_sync(0xffffffffu,t,o);
        if(tid==0) sm[33]=t;
    }
    __syncthreads();
    float inv = 1.f/sm[33];
    #pragma unroll
    for(int j=0;j<8;j++) p[tid+j*256]=v[j]*inv;
}

// ---------------- output proj + RevIN denorm ----------------
__global__ void k_final(const float* __restrict__ o, const float* __restrict__ w,
                        const float* __restrict__ ob, const float* __restrict__ rw,
                        const float* __restrict__ rb, float* __restrict__ out){
    int bt = blockIdx.x;
    int b  = bt >> 11;
    int e  = threadIdx.x;
    float x = o[(size_t)bt*E_ + e];
    float p0 = x*w[e], p1 = x*w[E_+e], p2 = x*w[2*E_+e];
    for(int s=16;s;s>>=1){
        p0 += __shfl_down_sync(0xffffffffu, p0, s);
        p1 += __shfl_down_sync(0xffffffffu, p1, s);
        p2 += __shfl_down_sync(0xffffffffu, p2, s);
    }
    __shared__ float sm[3][8];
    int wid=e>>5, lane=e&31;
    if(lane==0){ sm[0][wid]=p0; sm[1][wid]=p1; sm[2][wid]=p2; }
    __syncthreads();
    if(e < C_){
        float s=0.f;
        #pragma unroll
        for(int wdx=0;wdx<8;wdx++) s += sm[e][wdx];
        int c = e;
        float val = s + ob[c];
        val = (val - rb[c]) / rw[c];
        val = val * g_std[b*C_+c] + g_mean[b*C_+c];
        out[(size_t)bt*C_ + c] = val;
    }
}

// ---------------- host orchestration (graph-capturable) ----------------
template<int DIL>
static void launch_mid(const float* src, P3 wm, P3 bm, float* dst, int layer){
    size_t smem = (size_t)(WSZ + BN_*(128 + 14*DIL)) * sizeof(float);
    cudaFuncSetAttribute(k_conv_mid<DIL>, cudaFuncAttributeMaxDynamicSharedMemorySize, (int)smem);
    k_conv_mid<DIL><<<dim3(T_/128, B_, 3), 128, smem>>>(src, wm, bm, dst, layer);
}

extern "C" void kernel_launch(void* const* d_in, const int* in_sizes, int n_in,
                              void* d_out, int out_size){
    const float* query = (const float*)d_in[0];
    const float* key   = (const float*)d_in[1];
    const float* out_w = (const float*)d_in[20];
    const float* out_b = (const float*)d_in[21];
    const float* rw    = (const float*)d_in[22];
    const float* rb    = (const float*)d_in[23];

    float *p_qn,*p_kn,*p_h0,*p_h1,*p_q,*p_k,*p_v,*p_attn,*p_o;
    cudaGetSymbolAddress((void**)&p_qn,   g_qn);
    cudaGetSymbolAddress((void**)&p_kn,   g_kn);
    cudaGetSymbolAddress((void**)&p_h0,   g_h0);
    cudaGetSymbolAddress((void**)&p_h1,   g_h1);
    cudaGetSymbolAddress((void**)&p_q,    g_q);
    cudaGetSymbolAddress((void**)&p_k,    g_k);
    cudaGetSymbolAddress((void**)&p_v,    g_v);
    cudaGetSymbolAddress((void**)&p_attn, g_attn);
    cudaGetSymbolAddress((void**)&p_o,    g_o);

    P3 w_in  = {(const float*)d_in[2],  (const float*)d_in[8],  (const float*)d_in[14]};
    P3 b_in  = {(const float*)d_in[3],  (const float*)d_in[9],  (const float*)d_in[15]};
    P3 w_mid = {(const float*)d_in[4],  (const float*)d_in[10], (const float*)d_in[16]};
    P3 b_mid = {(const float*)d_in[5],  (const float*)d_in[11], (const float*)d_in[17]};
    P3 w_out = {(const float*)d_in[6],  (const float*)d_in[12], (const float*)d_in[18]};
    P3 b_out = {(const float*)d_in[7],  (const float*)d_in[13], (const float*)d_in[19]};

    k_stats<<<B_*C_, 256>>>(key);
    k_norm<<<(B_*C_*T_ + 255)/256, 256>>>(query, key, rw, rb);

    k_conv_in<<<dim3(T_/256, B_, 3), 256>>>(p_qn, p_kn, w_in, b_in, p_h0);
    launch_mid<2 >(p_h0, w_mid, b_mid, p_h1, 0);
    launch_mid<4 >(p_h1, w_mid, b_mid, p_h0, 1);
    launch_mid<8 >(p_h0, w_mid, b_mid, p_h1, 2);
    launch_mid<16>(p_h1, w_mid, b_mid, p_h0, 3);
    launch_mid<32>(p_h0, w_mid, b_mid, p_h1, 4);
    k_conv_out<<<dim3(T_/32, B_, 3), 256>>>(p_h1, w_out, b_out, p_q, p_k, p_v);

    // S = scale * Q K^T
    k_gemm_nt<<<dim3(T_/128, T_/128, B_), 256>>>(p_q, p_k, p_attn, T_, T_, E_,
        (size_t)T_*E_, (size_t)T_*E_, (size_t)T_*T_, 0.0625f);
    k_softmax<<<B_*T_, 256>>>(p_attn);
    // O = P V
    k_gemm_nn<<<dim3(T_/128, E_/64, B_), 256>>>(p_attn, p_v, p_o, T_, E_, T_,
        (size_t)T_*T_, (size_t)T_*E_, (size_t)T_*E_);
    k_final<<<B_*T_, 256>>>(p_o, out_w, out_b, rw, rb, (float*)d_out);
}

// round 3
// speedup vs baseline: 1.2954x; 1.0122x over previous
#include <cuda_runtime.h>
#include <math.h>

#define B_  8
#define T_  2048
#define C_  3
#define E_  256
#define K_  15
#define D_  5
#define BN_ 32
#define WSZ (BN_*BN_*K_)   // 15360 floats per mid layer

struct P3 { const float *q, *k, *v; };

__device__ __forceinline__ const float* pick(const P3& p, int net){
    return net==0 ? p.q : (net==1 ? p.k : p.v);
}

// ---------------- scratch (device globals; no allocs allowed) ----------------
static __device__ float g_mean[B_*C_];
static __device__ float g_std [B_*C_];
static __device__ float g_qn[B_*C_*T_];
static __device__ float g_kn[B_*C_*T_];
static __device__ float g_h0[3*B_*BN_*T_];
static __device__ float g_h1[3*B_*BN_*T_];
static __device__ float g_q[(size_t)B_*T_*E_];
static __device__ float g_k[(size_t)B_*T_*E_];
static __device__ float g_v[(size_t)B_*T_*E_];
static __device__ float g_attn[(size_t)B_*T_*T_];   // 128 MiB
static __device__ float g_o[(size_t)B_*T_*E_];

// ---------------- RevIN stats over time of key_in ----------------
__global__ void k_stats(const float* __restrict__ key){
    int bc = blockIdx.x, b = bc / C_, c = bc % C_;
    int tid = threadIdx.x;
    float s = 0.f, ss = 0.f;
    for (int t = tid; t < T_; t += 256){
        float x = key[((size_t)b*T_ + t)*C_ + c];
        s += x; ss += x*x;
    }
    __shared__ float r1[256], r2[256];
    r1[tid]=s; r2[tid]=ss; __syncthreads();
    for(int o=128;o;o>>=1){ if(tid<o){ r1[tid]+=r1[tid+o]; r2[tid]+=r2[tid+o]; } __syncthreads(); }
    if(tid==0){
        float m = r1[0]/(float)T_;
        float v = r2[0]/(float)T_ - m*m;
        g_mean[bc]=m;
        g_std[bc]=sqrtf(v + 1e-5f);
    }
}

// ---------------- normalize + transpose to [B][C][T] ----------------
__global__ void k_norm(const float* __restrict__ q, const float* __restrict__ k,
                       const float* __restrict__ rw, const float* __restrict__ rb){
    int i = blockIdx.x*256 + threadIdx.x;
    if(i >= B_*C_*T_) return;
    int t = i % T_, c = (i / T_) % C_, b = i / (C_*T_);
    float m = g_mean[b*C_+c], inv = 1.f/g_std[b*C_+c];
    float w = rw[c], bb = rb[c];
    size_t src = ((size_t)b*T_ + t)*C_ + c;
    g_qn[i] = (q[src]-m)*inv*w + bb;
    g_kn[i] = (k[src]-m)*inv*w + bb;
}

// ---------------- conv in (fused q/k/v): C_ -> BN_, K=15, dil=1, relu ------
__global__ void k_conv_in(const float* __restrict__ qn, const float* __restrict__ kn,
                          P3 w, P3 bias, float* __restrict__ dstbase){
    int net = blockIdx.z;
    const float* src = (net==0) ? qn : kn;
    const float* wp  = pick(w, net);
    const float* bp  = pick(bias, net);
    float* dst = dstbase + (size_t)net*B_*BN_*T_;

    __shared__ float ws[BN_*C_*K_];     // 1440
    __shared__ float bs[BN_];
    __shared__ float xs[C_][256 + K_ - 1];
    int b = blockIdx.y, t0 = blockIdx.x*256, tid = threadIdx.x;
    for(int i=tid;i<BN_*C_*K_;i+=256) ws[i]=wp[i];
    if(tid<BN_) bs[tid]=bp[tid];
    const int W = 256 + K_ - 1;
    for(int i=tid;i<C_*W;i+=256){
        int ci=i/W, p=i%W, g=t0+p-7;
        xs[ci][p] = ((unsigned)g < T_) ? src[(b*C_+ci)*T_ + g] : 0.f;
    }
    __syncthreads();
    float acc[BN_];
    #pragma unroll
    for(int c=0;c<BN_;c++) acc[c]=bs[c];
    #pragma unroll
    for(int ci=0;ci<C_;ci++){
        #pragma unroll
        for(int k=0;k<K_;k++){
            float x = xs[ci][tid+k];
            #pragma unroll
            for(int c=0;c<BN_;c++) acc[c] += x * ws[(c*C_+ci)*K_+k];
        }
    }
    int t = t0 + tid;
    #pragma unroll
    for(int c=0;c<BN_;c++) dst[((size_t)b*BN_+c)*T_ + t] = fmaxf(acc[c], 0.f);
}

// ---------------- conv mid (fused q/k/v): BN_ -> BN_, K=15, dilated, relu --
template<int DIL>
__global__ void k_conv_mid(const float* __restrict__ srcbase, P3 wm, P3 bm,
                           float* __restrict__ dstbase, int layer){
    constexpr int W = 128 + 14*DIL;
    constexpr int H = 7*DIL;
    extern __shared__ float sm[];
    float* ws = sm;           // WSZ floats, layout [ci*15+k][32]
    float* xs = sm + WSZ;     // 32 * W

    int net = blockIdx.z;
    const float* w    = pick(wm, net) + (size_t)layer*WSZ;
    const float* bias = pick(bm, net) + layer*BN_;
    const float* src  = srcbase + (size_t)net*B_*BN_*T_;
    float* dst        = dstbase + (size_t)net*B_*BN_*T_;

    int b = blockIdx.y, t0 = blockIdx.x*128, tid = threadIdx.x;

    for(int i=tid;i<WSZ;i+=128){
        int cout = i/480, rest = i - cout*480;
        ws[rest*BN_ + cout] = w[i];
    }
    for(int i=tid;i<BN_*W;i+=128){
        int ci = i/W, p = i - ci*W, g = t0 - H + p;
        xs[i] = ((unsigned)g < T_) ? src[(b*BN_+ci)*T_ + g] : 0.f;
    }
    __syncthreads();

    float acc[BN_];
    #pragma unroll
    for(int c=0;c<BN_;c++) acc[c]=__ldg(&bias[c]);

    for(int ci=0;ci<BN_;ci++){
        const float* xr = xs + ci*W + tid;
        #pragma unroll
        for(int k=0;k<K_;k++){
            float x = xr[k*DIL];
            const float4* wr = (const float4*)(ws + (ci*K_+k)*BN_);
            #pragma unroll
            for(int m=0;m<8;m++){
                float4 wv = wr[m];
                acc[4*m+0] += x*wv.x;
                acc[4*m+1] += x*wv.y;
                acc[4*m+2] += x*wv.z;
                acc[4*m+3] += x*wv.w;
            }
        }
    }
    int t = t0 + tid;
    #pragma unroll
    for(int c=0;c<BN_;c++) dst[((size_t)b*BN_+c)*T_ + t] = fmaxf(acc[c], 0.f);
}

// ---------------- conv out (fused, 1x1): BN_ -> E_, write [B][T][E] --------
__global__ void k_conv_out(const float* __restrict__ srcbase, P3 w, P3 bias,
                           float* __restrict__ qd, float* __restrict__ kd,
                           float* __restrict__ vd){
    int net = blockIdx.z;
    const float* src = srcbase + (size_t)net*B_*BN_*T_;
    const float* wp  = pick(w, net);
    const float* bp  = pick(bias, net);
    float* dst = (net==0) ? qd : (net==1 ? kd : vd);

    __shared__ float xs[BN_][32];
    int b = blockIdx.y, t0 = blockIdx.x*32, e = threadIdx.x;
    for(int i=e;i<BN_*32;i+=256){
        int ci=i>>5, tl=i&31;
        xs[ci][tl] = src[((size_t)b*BN_+ci)*T_ + t0 + tl];
    }
    __syncthreads();
    float acc[32];
    float bb = bp[e];
    #pragma unroll
    for(int t=0;t<32;t++) acc[t]=bb;
    #pragma unroll 4
    for(int ci=0;ci<BN_;ci++){
        float wv = __ldg(&wp[e*BN_+ci]);
        #pragma unroll
        for(int t=0;t<32;t++) acc[t] += xs[ci][t]*wv;
    }
    #pragma unroll
    for(int t=0;t<32;t++) dst[((size_t)b*T_ + t0+t)*E_ + e] = acc[t];
}

// =================== 3xTF32 tensor-core GEMMs ===================
__device__ __forceinline__ unsigned f2tf(float x){
    unsigned r; asm("cvt.rna.tf32.f32 %0, %1;" : "=r"(r) : "f"(x)); return r;
}
__device__ __forceinline__ void split_tf(float x, unsigned& h, unsigned& l){
    h = f2tf(x);
    l = f2tf(x - __uint_as_float(h));
}
__device__ __forceinline__ void mma8(float* c, const unsigned* a, unsigned b0, unsigned b1){
    asm volatile(
        "mma.sync.aligned.m16n8k8.row.col.f32.tf32.tf32.f32 "
        "{%0,%1,%2,%3},{%4,%5,%6,%7},{%8,%9},{%0,%1,%2,%3};"
        : "+f"(c[0]), "+f"(c[1]), "+f"(c[2]), "+f"(c[3])
        : "r"(a[0]), "r"(a[1]), "r"(a[2]), "r"(a[3]), "r"(b0), "r"(b1));
}

#define SKM 136   // padded smem leading dim (conflict-free fragment reads)

// Shared inner compute: As/Bs layout [k 0..15][m/n], warp = 32m x 64n
__device__ __forceinline__ void mma_chunk(
    const unsigned (*AsH)[SKM], const unsigned (*AsL)[SKM],
    const unsigned (*BsH)[SKM], const unsigned (*BsL)[SKM],
    float acc[16][4], int wm, int wn, int lane)
{
    int lq = lane >> 2, lr = lane & 3;
    #pragma unroll
    for(int ks=0; ks<2; ks++){
        int kb = ks*8 + lr;
        unsigned aH[2][4], aL[2][4];
        #pragma unroll
        for(int mt=0; mt<2; mt++){
            int rm = wm*32 + mt*16 + lq;
            aH[mt][0]=AsH[kb  ][rm];  aH[mt][1]=AsH[kb  ][rm+8];
            aH[mt][2]=AsH[kb+4][rm];  aH[mt][3]=AsH[kb+4][rm+8];
            aL[mt][0]=AsL[kb  ][rm];  aL[mt][1]=AsL[kb  ][rm+8];
            aL[mt][2]=AsL[kb+4][rm];  aL[mt][3]=AsL[kb+4][rm+8];
        }
        #pragma unroll
        for(int nt=0; nt<8; nt++){
            int cn = wn*64 + nt*8 + lq;
            unsigned bH0=BsH[kb][cn], bH1=BsH[kb+4][cn];
            unsigned bL0=BsL[kb][cn], bL1=BsL[kb+4][cn];
            #pragma unroll
            for(int mt=0; mt<2; mt++){
                mma8(acc[mt*8+nt], aH[mt], bH0, bH1);
                mma8(acc[mt*8+nt], aH[mt], bL0, bL1);
                mma8(acc[mt*8+nt], aL[mt], bH0, bH1);
            }
        }
    }
}

// NT: C[M,N] = alpha * A[M,K] * B[N,K]^T  (row-major, K contiguous; K=256)
__global__ void __launch_bounds__(256)
k_mma_nt(const float* __restrict__ A, const float* __restrict__ Bm,
         float* __restrict__ Cm, float alpha){
    __shared__ unsigned AsH[16][SKM], AsL[16][SKM], BsH[16][SKM], BsL[16][SKM];
    const int K = E_, N = T_;
    int bz = blockIdx.z;
    A  += (size_t)bz*T_*E_;
    Bm += (size_t)bz*T_*E_;
    Cm += (size_t)bz*T_*T_;
    int tid = threadIdx.x, lane = tid & 31, wid = tid >> 5;
    int wm = wid & 3, wn = wid >> 2;
    int row0 = blockIdx.x*128, col0 = blockIdx.y*128;

    float acc[16][4];
    #pragma unroll
    for(int i=0;i<16;i++){ acc[i][0]=acc[i][1]=acc[i][2]=acc[i][3]=0.f; }

    int r[2], c4[2];
    const float *pa[2], *pb[2];
    #pragma unroll
    for(int j=0;j<2;j++){
        int idx = tid + j*256;
        r[j] = idx>>2; c4[j] = (idx&3)<<2;
        pa[j] = A  + (size_t)(row0+r[j])*K + c4[j];
        pb[j] = Bm + (size_t)(col0+r[j])*K + c4[j];
    }
    float4 va[2], vb[2];
    #pragma unroll
    for(int j=0;j<2;j++){ va[j] = *(const float4*)pa[j]; vb[j] = *(const float4*)pb[j]; }

    const int NCH = K/16;
    for(int ch=0; ch<NCH; ch++){
        #pragma unroll
        for(int j=0;j<2;j++){
            unsigned h,l;
            split_tf(va[j].x,h,l); AsH[c4[j]+0][r[j]]=h; AsL[c4[j]+0][r[j]]=l;
            split_tf(va[j].y,h,l); AsH[c4[j]+1][r[j]]=h; AsL[c4[j]+1][r[j]]=l;
            split_tf(va[j].z,h,l); AsH[c4[j]+2][r[j]]=h; AsL[c4[j]+2][r[j]]=l;
            split_tf(va[j].w,h,l); AsH[c4[j]+3][r[j]]=h; AsL[c4[j]+3][r[j]]=l;
            split_tf(vb[j].x,h,l); BsH[c4[j]+0][r[j]]=h; BsL[c4[j]+0][r[j]]=l;
            split_tf(vb[j].y,h,l); BsH[c4[j]+1][r[j]]=h; BsL[c4[j]+1][r[j]]=l;
            split_tf(vb[j].z,h,l); BsH[c4[j]+2][r[j]]=h; BsL[c4[j]+2][r[j]]=l;
            split_tf(vb[j].w,h,l); BsH[c4[j]+3][r[j]]=h; BsL[c4[j]+3][r[j]]=l;
        }
        __syncthreads();
        if(ch+1 < NCH){
            #pragma unroll
            for(int j=0;j<2;j++){
                va[j] = *(const float4*)(pa[j] + (ch+1)*16);
                vb[j] = *(const float4*)(pb[j] + (ch+1)*16);
            }
        }
        mma_chunk(AsH, AsL, BsH, BsL, acc, wm, wn, lane);
        __syncthreads();
    }
    int lq = lane>>2, lr = lane&3;
    #pragma unroll
    for(int mt=0; mt<2; mt++){
        #pragma unroll
        for(int nt=0; nt<8; nt++){
            int row = row0 + wm*32 + mt*16 + lq;
            int col = col0 + wn*64 + nt*8 + lr*2;
            float* c = acc[mt*8+nt];
            *(float2*)(Cm + (size_t)row*N + col)     = make_float2(c[0]*alpha, c[1]*alpha);
            *(float2*)(Cm + (size_t)(row+8)*N + col) = make_float2(c[2]*alpha, c[3]*alpha);
        }
    }
}

// NN: C[M,N] = A[M,K] * B[K,N]  (row-major; M=2048, K=2048, N=256)
__global__ void __launch_bounds__(256)
k_mma_nn(const float* __restrict__ A, const float* __restrict__ Bm,
         float* __restrict__ Cm){
    __shared__ unsigned AsH[16][SKM], AsL[16][SKM], BsH[16][SKM], BsL[16][SKM];
    const int K = T_, N = E_;
    int bz = blockIdx.z;
    A  += (size_t)bz*T_*T_;
    Bm += (size_t)bz*T_*E_;
    Cm += (size_t)bz*T_*E_;
    int tid = threadIdx.x, lane = tid & 31, wid = tid >> 5;
    int wm = wid & 3, wn = wid >> 2;
    int row0 = blockIdx.x*128, col0 = blockIdx.y*128;

    float acc[16][4];
    #pragma unroll
    for(int i=0;i<16;i++){ acc[i][0]=acc[i][1]=acc[i][2]=acc[i][3]=0.f; }

    int r[2], c4[2], kr[2], nc[2];
    const float *pa[2], *pb[2];
    #pragma unroll
    for(int j=0;j<2;j++){
        int idx = tid + j*256;
        r[j] = idx>>2; c4[j] = (idx&3)<<2;         // A: 128 rows x 16 k
        kr[j] = idx>>5; nc[j] = (idx&31)<<2;       // B: 16 k x 128 n
        pa[j] = A  + (size_t)(row0+r[j])*K + c4[j];
        pb[j] = Bm + (size_t)kr[j]*N + col0 + nc[j];
    }
    float4 va[2], vb[2];
    #pragma unroll
    for(int j=0;j<2;j++){ va[j] = *(const float4*)pa[j]; vb[j] = *(const float4*)pb[j]; }

    const int NCH = K/16;
    for(int ch=0; ch<NCH; ch++){
        #pragma unroll
        for(int j=0;j<2;j++){
            unsigned h,l;
            split_tf(va[j].x,h,l); AsH[c4[j]+0][r[j]]=h; AsL[c4[j]+0][r[j]]=l;
            split_tf(va[j].y,h,l); AsH[c4[j]+1][r[j]]=h; AsL[c4[j]+1][r[j]]=l;
            split_tf(va[j].z,h,l); AsH[c4[j]+2][r[j]]=h; AsL[c4[j]+2][r[j]]=l;
            split_tf(va[j].w,h,l); AsH[c4[j]+3][r[j]]=h; AsL[c4[j]+3][r[j]]=l;
            unsigned h0,l0,h1,l1,h2,l2,h3,l3;
            split_tf(vb[j].x,h0,l0); split_tf(vb[j].y,h1,l1);
            split_tf(vb[j].z,h2,l2); split_tf(vb[j].w,h3,l3);
            *(uint4*)&BsH[kr[j]][nc[j]] = make_uint4(h0,h1,h2,h3);
            *(uint4*)&BsL[kr[j]][nc[j]] = make_uint4(l0,l1,l2,l3);
        }
        __syncthreads();
        if(ch+1 < NCH){
            #pragma unroll
            for(int j=0;j<2;j++){
                va[j] = *(const float4*)(pa[j] + (ch+1)*16);
                vb[j] = *(const float4*)(pb[j] + (size_t)(ch+1)*16*N);
            }
        }
        mma_chunk(AsH, AsL, BsH, BsL, acc, wm, wn, lane);
        __syncthreads();
    }
    int lq = lane>>2, lr = lane&3;
    #pragma unroll
    for(int mt=0; mt<2; mt++){
        #pragma unroll
        for(int nt=0; nt<8; nt++){
            int row = row0 + wm*32 + mt*16 + lq;
            int col = col0 + wn*64 + nt*8 + lr*2;
            float* c = acc[mt*8+nt];
            *(float2*)(Cm + (size_t)row*N + col)     = make_float2(c[0], c[1]);
            *(float2*)(Cm + (size_t)(row+8)*N + col) = make_float2(c[2], c[3]);
        }
    }
}

// ---------------- row softmax over T_ ----------------
__global__ void k_softmax(float* __restrict__ S){
    size_t row = blockIdx.x;
    float* p = S + row*T_;
    int tid = threadIdx.x;
    float v[8];
    #pragma unroll
    for(int j=0;j<8;j++) v[j] = p[tid + j*256];
    float m = v[0];
    #pragma unroll
    for(int j=1;j<8;j++) m = fmaxf(m, v[j]);
    __shared__ float sm[40];
    for(int o=16;o;o>>=1) m = fmaxf(m, __shfl_xor_sync(0xffffffffu, m, o));
    if((tid&31)==0) sm[tid>>5] = m;
    __syncthreads();
    if(tid<32){
        float t = (tid<8)?sm[tid]:-3.0e38f;
        for(int o=4;o;o>>=1) t=fmaxf(t,__shfl_xor_sync(0xffffffffu,t,o));
        if(tid==0) sm[32]=t;
    }
    __syncthreads();
    m = sm[32];
    float s=0.f;
    #pragma unroll
    for(int j=0;j<8;j++){ v[j]=__expf(v[j]-m); s+=v[j]; }
    for(int o=16;o;o>>=1) s += __shfl_xor_sync(0xffffffffu, s, o);
    if((tid&31)==0) sm[tid>>5] = s;
    __syncthreads();
    if(tid<32){
        float t=(tid<8)?sm[tid]:0.f;
        for(int o=4;o;o>>=1) t+=__shfl_xor_sync(0xffffffffu,t,o);
        if(tid==0) sm[33]=t;
    }
    __syncthreads();
    float inv = 1.f/sm[33];
    #pragma unroll
    for(int j=0;j<8;j++) p[tid+j*256]=v[j]*inv;
}

// ---------------- output proj + RevIN denorm ----------------
__global__ void k_final(const float* __restrict__ o, const float* __restrict__ w,
                        const float* __restrict__ ob, const float* __restrict__ rw,
                        const float* __restrict__ rb, float* __restrict__ out){
    int bt = blockIdx.x;
    int b  = bt >> 11;
    int e  = threadIdx.x;
    float x = o[(size_t)bt*E_ + e];
    float p0 = x*w[e], p1 = x*w[E_+e], p2 = x*w[2*E_+e];
    for(int s=16;s;s>>=1){
        p0 += __shfl_down_sync(0xffffffffu, p0, s);
        p1 += __shfl_down_sync(0xffffffffu, p1, s);
        p2 += __shfl_down_sync(0xffffffffu, p2, s);
    }
    __shared__ float sm[3][8];
    int wid=e>>5, lane=e&31;
    if(lane==0){ sm[0][wid]=p0; sm[1][wid]=p1; sm[2][wid]=p2; }
    __syncthreads();
    if(e < C_){
        float s=0.f;
        #pragma unroll
        for(int wdx=0;wdx<8;wdx++) s += sm[e][wdx];
        int c = e;
        float val = s + ob[c];
        val = (val - rb[c]) / rw[c];
        val = val * g_std[b*C_+c] + g_mean[b*C_+c];
        out[(size_t)bt*C_ + c] = val;
    }
}

// ---------------- host orchestration (graph-capturable) ----------------
template<int DIL>
static void launch_mid(const float* src, P3 wm, P3 bm, float* dst, int layer){
    size_t smem = (size_t)(WSZ + BN_*(128 + 14*DIL)) * sizeof(float);
    cudaFuncSetAttribute(k_conv_mid<DIL>, cudaFuncAttributeMaxDynamicSharedMemorySize, (int)smem);
    k_conv_mid<DIL><<<dim3(T_/128, B_, 3), 128, smem>>>(src, wm, bm, dst, layer);
}

extern "C" void kernel_launch(void* const* d_in, const int* in_sizes, int n_in,
                              void* d_out, int out_size){
    const float* query = (const float*)d_in[0];
    const float* key   = (const float*)d_in[1];
    const float* out_w = (const float*)d_in[20];
    const float* out_b = (const float*)d_in[21];
    const float* rw    = (const float*)d_in[22];
    const float* rb    = (const float*)d_in[23];

    float *p_qn,*p_kn,*p_h0,*p_h1,*p_q,*p_k,*p_v,*p_attn,*p_o;
    cudaGetSymbolAddress((void**)&p_qn,   g_qn);
    cudaGetSymbolAddress((void**)&p_kn,   g_kn);
    cudaGetSymbolAddress((void**)&p_h0,   g_h0);
    cudaGetSymbolAddress((void**)&p_h1,   g_h1);
    cudaGetSymbolAddress((void**)&p_q,    g_q);
    cudaGetSymbolAddress((void**)&p_k,    g_k);
    cudaGetSymbolAddress((void**)&p_v,    g_v);
    cudaGetSymbolAddress((void**)&p_attn, g_attn);
    cudaGetSymbolAddress((void**)&p_o,    g_o);

    P3 w_in  = {(const float*)d_in[2],  (const float*)d_in[8],  (const float*)d_in[14]};
    P3 b_in  = {(const float*)d_in[3],  (const float*)d_in[9],  (const float*)d_in[15]};
    P3 w_mid = {(const float*)d_in[4],  (const float*)d_in[10], (const float*)d_in[16]};
    P3 b_mid = {(const float*)d_in[5],  (const float*)d_in[11], (const float*)d_in[17]};
    P3 w_out = {(const float*)d_in[6],  (const float*)d_in[12], (const float*)d_in[18]};
    P3 b_out = {(const float*)d_in[7],  (const float*)d_in[13], (const float*)d_in[19]};

    k_stats<<<B_*C_, 256>>>(key);
    k_norm<<<(B_*C_*T_ + 255)/256, 256>>>(query, key, rw, rb);

    k_conv_in<<<dim3(T_/256, B_, 3), 256>>>(p_qn, p_kn, w_in, b_in, p_h0);
    launch_mid<2 >(p_h0, w_mid, b_mid, p_h1, 0);
    launch_mid<4 >(p_h1, w_mid, b_mid, p_h0, 1);
    launch_mid<8 >(p_h0, w_mid, b_mid, p_h1, 2);
    launch_mid<16>(p_h1, w_mid, b_mid, p_h0, 3);
    launch_mid<32>(p_h0, w_mid, b_mid, p_h1, 4);
    k_conv_out<<<dim3(T_/32, B_, 3), 256>>>(p_h1, w_out, b_out, p_q, p_k, p_v);

    // S = scale * Q K^T   (3xTF32 tensor cores)
    k_mma_nt<<<dim3(T_/128, T_/128, B_), 256>>>(p_q, p_k, p_attn, 0.0625f);
    k_softmax<<<B_*T_, 256>>>(p_attn);
    // O = P V             (3xTF32 tensor cores)
    k_mma_nn<<<dim3(T_/128, E_/128, B_), 256>>>(p_attn, p_v, p_o);
    k_final<<<B_*T_, 256>>>(p_o, out_w, out_b, rw, rb, (float*)d_out);
}